// round 2
// baseline (speedup 1.0000x reference)
#include <cuda_runtime.h>
#include <math.h>

#define HIDDEN   640
#define ATTN_DIM 128
#define LN_EPS   1e-5f
#define C_CHUNKS 40          // chunks per batch in flash pass
#define TB       8           // tokens per group (per block-reduce round)
#define FLASH_THREADS 160    // 160 * float4 = 640 hidden elems
#define B_MAX    32
#define C_MAX    64

// Scratch (static device globals — no allocation allowed)
__device__ float g_qk[B_MAX * HIDDEN];                    // scaled query-key fold vector per batch
__device__ float g_pm[B_MAX * C_MAX];                     // per-chunk running max
__device__ float g_ps[B_MAX * C_MAX];                     // per-chunk exp-sum
__device__ float g_pacc[B_MAX * C_MAX * HIDDEN];          // per-chunk weighted accumulators

// ---------------------------------------------------------------------------
// Kernel 0: qk[b,h] = scale * sum_a (gp[b]·Wq[a,:]) * Wk[a,h]
// grid = B, block = 640
// ---------------------------------------------------------------------------
__global__ void k_qk(const float* __restrict__ gp,
                     const float* __restrict__ Wq,
                     const float* __restrict__ Wk) {
    __shared__ float sh_gp[HIDDEN];
    __shared__ float sh_q[ATTN_DIM];
    const int b = blockIdx.x;
    const int t = threadIdx.x;

    sh_gp[t] = gp[b * HIDDEN + t];
    __syncthreads();

    if (t < ATTN_DIM) {
        float acc = 0.f;
        const float* wrow = Wq + (size_t)t * HIDDEN;
        #pragma unroll 4
        for (int h = 0; h < HIDDEN; ++h) acc += sh_gp[h] * wrow[h];
        sh_q[t] = acc * rsqrtf((float)ATTN_DIM);   // fold softmax scale into q
    }
    __syncthreads();

    float acc = 0.f;
    #pragma unroll 4
    for (int a = 0; a < ATTN_DIM; ++a) acc += sh_q[a] * Wk[(size_t)a * HIDDEN + t];
    g_qk[b * HIDDEN + t] = acc;
}

// ---------------------------------------------------------------------------
// Kernel 1: single streaming pass over gene_hiddens with online softmax.
// Each CTA handles one (batch, token-chunk). Per token:
//   score = gh[b,n,:] . qk[b,:]           (block dot-reduce)
//   acc  += exp(score - m) * gh[b,n,:]    (online-rescaled)
// grid = B * C, block = 160 (each thread owns 4 consecutive hidden elems)
// ---------------------------------------------------------------------------
__global__ __launch_bounds__(FLASH_THREADS)
void k_flash(const float* __restrict__ gh, int N, int chunk, int C) {
    const int b  = blockIdx.x / C;
    const int c  = blockIdx.x % C;
    const int n0 = c * chunk;
    const int n1 = min(N, n0 + chunk);
    const int t    = threadIdx.x;
    const int lane = t & 31;
    const int wid  = t >> 5;

    __shared__ float warp_p[FLASH_THREADS / 32][TB];

    const float4 qk = *(const float4*)(g_qk + b * HIDDEN + 4 * t);
    float4 acc = make_float4(0.f, 0.f, 0.f, 0.f);
    float  m = -1e30f, s = 0.f;

    const float* base = gh + (size_t)b * N * HIDDEN + 4 * t;

    for (int n = n0; n < n1; n += TB) {
        float4 x[TB];
        float  p[TB];
        #pragma unroll
        for (int i = 0; i < TB; ++i) {
            const int nn = n + i;
            if (nn < n1) x[i] = *(const float4*)(base + (size_t)nn * HIDDEN);
            else         x[i] = make_float4(0.f, 0.f, 0.f, 0.f);
            p[i] = x[i].x * qk.x + x[i].y * qk.y + x[i].z * qk.z + x[i].w * qk.w;
        }
        // warp-level reduce each of the TB partial dots
        #pragma unroll
        for (int i = 0; i < TB; ++i) {
            #pragma unroll
            for (int off = 16; off > 0; off >>= 1)
                p[i] += __shfl_xor_sync(0xffffffffu, p[i], off);
        }
        if (lane == 0) {
            #pragma unroll
            for (int i = 0; i < TB; ++i) warp_p[wid][i] = p[i];
        }
        __syncthreads();

        float sc[TB];
        #pragma unroll
        for (int i = 0; i < TB; ++i) {
            sc[i] = warp_p[0][i] + warp_p[1][i] + warp_p[2][i]
                  + warp_p[3][i] + warp_p[4][i];
            if (n + i >= n1) sc[i] = -1e30f;   // mask tail tokens
        }
        __syncthreads();   // before warp_p is overwritten next group

        float gm = sc[0];
        #pragma unroll
        for (int i = 1; i < TB; ++i) gm = fmaxf(gm, sc[i]);
        if (gm > m) {
            const float f = (m > -1e29f) ? __expf(m - gm) : 0.f;
            acc.x *= f; acc.y *= f; acc.z *= f; acc.w *= f;
            s *= f;
            m = gm;
        }
        #pragma unroll
        for (int i = 0; i < TB; ++i) {
            const float w = __expf(sc[i] - m);
            s += w;
            acc.x += w * x[i].x;
            acc.y += w * x[i].y;
            acc.z += w * x[i].z;
            acc.w += w * x[i].w;
        }
    }

    const int pid = blockIdx.x;     // == b*C + c
    if (t == 0) { g_pm[pid] = m; g_ps[pid] = s; }
    *(float4*)(g_pacc + (size_t)pid * HIDDEN + 4 * t) = acc;
}

// ---------------------------------------------------------------------------
// Kernel 2: combine chunk partials -> pooled[b,:], then y = Wv @ pooled, LN.
// grid = B, block = 640
// ---------------------------------------------------------------------------
__global__ void k_final(const float* __restrict__ Wv,
                        const float* __restrict__ gamma,
                        const float* __restrict__ beta,
                        float* __restrict__ out, int C) {
    const int b = blockIdx.x;
    const int v = threadIdx.x;
    const int lane = v & 31;
    const int wid  = v >> 5;

    __shared__ float sh_m[C_MAX], sh_s[C_MAX], sh_coef[C_MAX];
    __shared__ float sh_pooled[HIDDEN];
    __shared__ float red[HIDDEN / 32];
    __shared__ float sh_stat;

    if (v < C) { sh_m[v] = g_pm[b * C + v]; sh_s[v] = g_ps[b * C + v]; }
    __syncthreads();

    float M = -1e30f;
    for (int c0 = 0; c0 < C; ++c0) M = fmaxf(M, sh_m[c0]);
    float S = 0.f;
    for (int c0 = 0; c0 < C; ++c0) S += expf(sh_m[c0] - M) * sh_s[c0];
    if (v < C) sh_coef[v] = expf(sh_m[v] - M);
    __syncthreads();

    float pooled = 0.f;
    for (int c0 = 0; c0 < C; ++c0)
        pooled += sh_coef[c0] * g_pacc[(size_t)(b * C + c0) * HIDDEN + v];
    pooled /= S;
    sh_pooled[v] = pooled;
    __syncthreads();

    // y[v] = Wv[v,:] . pooled
    float y = 0.f;
    const float4* wrow = (const float4*)(Wv + (size_t)v * HIDDEN);
    #pragma unroll 4
    for (int h4 = 0; h4 < HIDDEN / 4; ++h4) {
        const float4 w = wrow[h4];
        y += w.x * sh_pooled[4 * h4 + 0] + w.y * sh_pooled[4 * h4 + 1]
           + w.z * sh_pooled[4 * h4 + 2] + w.w * sh_pooled[4 * h4 + 3];
    }

    // LayerNorm over the 640 y values (two-pass: mean, then centered var)
    float sum = y;
    #pragma unroll
    for (int off = 16; off > 0; off >>= 1) sum += __shfl_xor_sync(0xffffffffu, sum, off);
    if (lane == 0) red[wid] = sum;
    __syncthreads();
    if (v == 0) {
        float a = 0.f;
        for (int w2 = 0; w2 < HIDDEN / 32; ++w2) a += red[w2];
        sh_stat = a / HIDDEN;
    }
    __syncthreads();
    const float mu = sh_stat;
    const float d  = y - mu;
    float sq = d * d;
    #pragma unroll
    for (int off = 16; off > 0; off >>= 1) sq += __shfl_xor_sync(0xffffffffu, sq, off);
    __syncthreads();   // red reuse
    if (lane == 0) red[wid] = sq;
    __syncthreads();
    if (v == 0) {
        float a = 0.f;
        for (int w2 = 0; w2 < HIDDEN / 32; ++w2) a += red[w2];
        sh_stat = a / HIDDEN;
    }
    __syncthreads();
    const float var = sh_stat;

    out[b * HIDDEN + v] = d * rsqrtf(var + LN_EPS) * gamma[v] + beta[v];
}

// ---------------------------------------------------------------------------
extern "C" void kernel_launch(void* const* d_in, const int* in_sizes, int n_in,
                              void* d_out, int out_size) {
    const float* gh    = (const float*)d_in[0];  // [B, N, 640]
    const float* gp    = (const float*)d_in[1];  // [B, 640]
    const float* Wq    = (const float*)d_in[2];  // [128, 640]
    const float* Wk    = (const float*)d_in[3];  // [128, 640]
    const float* Wv    = (const float*)d_in[4];  // [640, 640]
    const float* gamma = (const float*)d_in[5];  // [640]
    const float* beta  = (const float*)d_in[6];  // [640]

    const int B = in_sizes[1] / HIDDEN;
    const int N = in_sizes[0] / (B * HIDDEN);
    const int C = C_CHUNKS;
    const int chunk = (N + C - 1) / C;

    k_qk<<<B, HIDDEN>>>(gp, Wq, Wk);
    k_flash<<<B * C, FLASH_THREADS>>>(gh, N, chunk, C);
    k_final<<<B, HIDDEN>>>(Wv, gamma, beta, (float*)d_out, C);
}

// round 3
// speedup vs baseline: 1.1348x; 1.1348x over previous
#include <cuda_runtime.h>
#include <math.h>

#define HIDDEN     640
#define H4         (HIDDEN / 4)     // 160 float4 per row
#define ATTN_DIM   128
#define LN_EPS     1e-5f
#define CTAS_PER_B 28               // flash CTAs per batch
#define WARPS      8                // warps per flash CTA
#define CW         (CTAS_PER_B * WARPS)   // 224 warp-chunks per batch
#define B_MAX      32
#define CW_MAX     256

// Static device scratch (no allocations allowed)
__device__ float g_qk[B_MAX * HIDDEN];                       // folded scale*Wk^T*Wq*gp per batch
__device__ float g_pm[B_MAX * CW_MAX];                       // per-warp-chunk running max
__device__ float g_ps[B_MAX * CW_MAX];                       // per-warp-chunk exp-sum
__device__ float g_pacc[(size_t)B_MAX * CW_MAX * HIDDEN];    // per-warp-chunk weighted acc

// ---------------------------------------------------------------------------
// Kernel 0 (fused, coalesced): qk[b,:] = scale * Wk^T (Wq gp[b])
// grid = B, block = 512.
// Phase 1: warp-per-row dot (lane-split float4, coalesced) -> q[128] in smem.
// Phase 2: thread-per-h column sum over Wk (coalesced across h).
// ---------------------------------------------------------------------------
__global__ __launch_bounds__(512)
void k_qk(const float* __restrict__ gp,
          const float* __restrict__ Wq,
          const float* __restrict__ Wk) {
    __shared__ float sh_gp[HIDDEN];
    __shared__ float sh_q[ATTN_DIM];
    const int b    = blockIdx.x;
    const int t    = threadIdx.x;
    const int lane = t & 31;
    const int wid  = t >> 5;          // 16 warps

    for (int i = t; i < HIDDEN; i += 512) sh_gp[i] = gp[b * HIDDEN + i];
    __syncthreads();

    // Phase 1: each of 16 warps computes 8 rows of q = Wq @ gp
    const float4* sgp4 = (const float4*)sh_gp;
    for (int k = 0; k < 8; ++k) {
        const int a = wid * 8 + k;    // 0..127
        const float4* wrow = (const float4*)(Wq + (size_t)a * HIDDEN);
        float p = 0.f;
        #pragma unroll
        for (int j = 0; j < 5; ++j) {
            const float4 w = wrow[lane + 32 * j];
            const float4 g = sgp4[lane + 32 * j];
            p += w.x * g.x + w.y * g.y + w.z * g.z + w.w * g.w;
        }
        #pragma unroll
        for (int off = 16; off > 0; off >>= 1)
            p += __shfl_xor_sync(0xffffffffu, p, off);
        if (lane == 0) sh_q[a] = p * rsqrtf((float)ATTN_DIM);  // fold softmax scale
    }
    __syncthreads();

    // Phase 2: qk[h] = sum_a q[a] * Wk[a,h]   (coalesced: consecutive t -> consecutive h)
    for (int h = t; h < HIDDEN; h += 512) {
        float a0 = 0.f, a1 = 0.f, a2 = 0.f, a3 = 0.f;
        #pragma unroll 4
        for (int a = 0; a < ATTN_DIM; a += 4) {
            a0 += sh_q[a + 0] * Wk[(size_t)(a + 0) * HIDDEN + h];
            a1 += sh_q[a + 1] * Wk[(size_t)(a + 1) * HIDDEN + h];
            a2 += sh_q[a + 2] * Wk[(size_t)(a + 2) * HIDDEN + h];
            a3 += sh_q[a + 3] * Wk[(size_t)(a + 3) * HIDDEN + h];
        }
        g_qk[b * HIDDEN + h] = (a0 + a1) + (a2 + a3);
    }
}

// ---------------------------------------------------------------------------
// Kernel 1: warp-autonomous streaming flash pass. No shared, no barriers.
// Lane l owns float4 columns {l, l+32, l+64, l+96, l+128} of each 640-row.
// grid = B * CTAS_PER_B, block = 256 (8 independent warps).
// ---------------------------------------------------------------------------
__global__ __launch_bounds__(256, 3)
void k_flash(const float* __restrict__ gh, int N, int tpw, int C) {
    const int b    = blockIdx.x / C;
    const int c    = blockIdx.x % C;
    const int lane = threadIdx.x & 31;
    const int wid  = threadIdx.x >> 5;
    const int wc   = c * WARPS + wid;              // warp-chunk id within batch

    const long n0 = (long)wc * tpw;
    const long n1 = (long)min((long long)N, (long long)(n0 + tpw));

    float4 q0, q1, q2, q3, q4;
    {
        const float4* qk = (const float4*)(g_qk + b * HIDDEN) + lane;
        q0 = qk[0]; q1 = qk[32]; q2 = qk[64]; q3 = qk[96]; q4 = qk[128];
    }
    float4 a0 = make_float4(0.f,0.f,0.f,0.f), a1 = a0, a2 = a0, a3 = a0, a4 = a0;
    float m = -1e30f, s = 0.f;

    const float4* base = (const float4*)gh + (size_t)b * N * H4 + lane;

    for (long n = n0; n < n1; ++n) {
        const float4* row = base + n * H4;
        const float4 x0 = row[0], x1 = row[32], x2 = row[64], x3 = row[96], x4 = row[128];

        float p = x0.x*q0.x + x0.y*q0.y + x0.z*q0.z + x0.w*q0.w;
        p += x1.x*q1.x + x1.y*q1.y + x1.z*q1.z + x1.w*q1.w;
        p += x2.x*q2.x + x2.y*q2.y + x2.z*q2.z + x2.w*q2.w;
        p += x3.x*q3.x + x3.y*q3.y + x3.z*q3.z + x3.w*q3.w;
        p += x4.x*q4.x + x4.y*q4.y + x4.z*q4.z + x4.w*q4.w;
        #pragma unroll
        for (int off = 16; off > 0; off >>= 1)
            p += __shfl_xor_sync(0xffffffffu, p, off);

        if (p > m) {                 // warp-uniform branch, ~log(tokens) hits
            const float f = __expf(m - p);
            s *= f;
            a0.x*=f; a0.y*=f; a0.z*=f; a0.w*=f;
            a1.x*=f; a1.y*=f; a1.z*=f; a1.w*=f;
            a2.x*=f; a2.y*=f; a2.z*=f; a2.w*=f;
            a3.x*=f; a3.y*=f; a3.z*=f; a3.w*=f;
            a4.x*=f; a4.y*=f; a4.z*=f; a4.w*=f;
            m = p;
        }
        const float w = __expf(p - m);
        s += w;
        a0.x += w*x0.x; a0.y += w*x0.y; a0.z += w*x0.z; a0.w += w*x0.w;
        a1.x += w*x1.x; a1.y += w*x1.y; a1.z += w*x1.z; a1.w += w*x1.w;
        a2.x += w*x2.x; a2.y += w*x2.y; a2.z += w*x2.z; a2.w += w*x2.w;
        a3.x += w*x3.x; a3.y += w*x3.y; a3.z += w*x3.z; a3.w += w*x3.w;
        a4.x += w*x4.x; a4.y += w*x4.y; a4.z += w*x4.z; a4.w += w*x4.w;
    }

    const int pid = b * CW + wc;
    if (lane == 0) { g_pm[pid] = m; g_ps[pid] = s; }
    float4* o = (float4*)(g_pacc + (size_t)pid * HIDDEN) + lane;
    o[0] = a0; o[32] = a1; o[64] = a2; o[96] = a3; o[128] = a4;
}

// ---------------------------------------------------------------------------
// Kernel 2: merge warp-chunk partials -> pooled, Wv GEMV, LayerNorm.
// grid = B, block = 640.
// ---------------------------------------------------------------------------
__global__ __launch_bounds__(HIDDEN)
void k_final(const float* __restrict__ Wv,
             const float* __restrict__ gamma,
             const float* __restrict__ beta,
             float* __restrict__ out, int C) {
    const int b    = blockIdx.x;
    const int v    = threadIdx.x;
    const int lane = v & 31;
    const int wid  = v >> 5;

    __shared__ float sh_m[CW_MAX], sh_coef[CW_MAX];
    __shared__ float sh_pooled[HIDDEN];
    __shared__ float red[HIDDEN / 32];
    __shared__ float sh_stat;

    if (v < C) sh_m[v] = g_pm[b * C + v];
    __syncthreads();

    float M = -1e30f;
    for (int c0 = 0; c0 < C; ++c0) M = fmaxf(M, sh_m[c0]);
    if (v < C) sh_coef[v] = expf(sh_m[v] - M);
    __syncthreads();

    float S = 0.f;
    for (int c0 = 0; c0 < C; ++c0) S += sh_coef[c0] * g_ps[b * C + c0];

    float pooled = 0.f;
    const float* pa = g_pacc + (size_t)b * C * HIDDEN + v;
    #pragma unroll 4
    for (int c0 = 0; c0 < C; ++c0)
        pooled += sh_coef[c0] * pa[(size_t)c0 * HIDDEN];
    pooled /= S;
    sh_pooled[v] = pooled;
    __syncthreads();

    // y[v] = Wv[v,:] . pooled
    float y = 0.f;
    const float4* wrow = (const float4*)(Wv + (size_t)v * HIDDEN);
    const float4* sp4  = (const float4*)sh_pooled;
    #pragma unroll 4
    for (int h4 = 0; h4 < H4; ++h4) {
        const float4 w = wrow[h4];
        const float4 g = sp4[h4];
        y += w.x*g.x + w.y*g.y + w.z*g.z + w.w*g.w;
    }

    // LayerNorm across the 640 y values
    float sum = y;
    #pragma unroll
    for (int off = 16; off > 0; off >>= 1) sum += __shfl_xor_sync(0xffffffffu, sum, off);
    if (lane == 0) red[wid] = sum;
    __syncthreads();
    if (v == 0) {
        float a = 0.f;
        for (int w2 = 0; w2 < HIDDEN / 32; ++w2) a += red[w2];
        sh_stat = a / HIDDEN;
    }
    __syncthreads();
    const float mu = sh_stat;
    const float d  = y - mu;
    float sq = d * d;
    #pragma unroll
    for (int off = 16; off > 0; off >>= 1) sq += __shfl_xor_sync(0xffffffffu, sq, off);
    __syncthreads();
    if (lane == 0) red[wid] = sq;
    __syncthreads();
    if (v == 0) {
        float a = 0.f;
        for (int w2 = 0; w2 < HIDDEN / 32; ++w2) a += red[w2];
        sh_stat = a / HIDDEN;
    }
    __syncthreads();

    out[b * HIDDEN + v] = d * rsqrtf(sh_stat + LN_EPS) * gamma[v] + beta[v];
}

// ---------------------------------------------------------------------------
extern "C" void kernel_launch(void* const* d_in, const int* in_sizes, int n_in,
                              void* d_out, int out_size) {
    const float* gh    = (const float*)d_in[0];  // [B, N, 640]
    const float* gp    = (const float*)d_in[1];  // [B, 640]
    const float* Wq    = (const float*)d_in[2];  // [128, 640]
    const float* Wk    = (const float*)d_in[3];  // [128, 640]
    const float* Wv    = (const float*)d_in[4];  // [640, 640]
    const float* gamma = (const float*)d_in[5];  // [640]
    const float* beta  = (const float*)d_in[6];  // [640]

    const int B = in_sizes[1] / HIDDEN;
    const int N = in_sizes[0] / (B * HIDDEN);
    const int tpw = (N + CW - 1) / CW;           // tokens per warp-chunk

    k_qk<<<B, 512>>>(gp, Wq, Wk);
    k_flash<<<B * CTAS_PER_B, 256>>>(gh, N, tpw, CTAS_PER_B);
    k_final<<<B, HIDDEN>>>(Wv, gamma, beta, (float*)d_out, CW);
}